// round 2
// baseline (speedup 1.0000x reference)
#include <cuda_runtime.h>

#define NN 50000
#define NE 800000
#define F  64
#define NLAYERS 3

#define TE 128          // edges per block in edge kernel
#define PAD 65          // h1 smem row pad

// scratch (device globals: no allocation allowed)
__device__ float g_u [NN * F];
__device__ float g_v [NN * F];
__device__ float g_x1[NN * F];
__device__ float g_x2[NN * F];

// ---------------------------------------------------------------------------
// Node kernel: u = x@(W1a - W1b) + b1 ;  v = x@W1b
// 32 nodes per block, W1 (32KB) staged in smem.
// thread handles 2 cols x 4 nodes.
// ---------------------------------------------------------------------------
__global__ __launch_bounds__(256) void node_kernel(
    const float* __restrict__ x,
    const float* __restrict__ W1,   // [128,64] row-major
    const float* __restrict__ b1g,  // [64]
    float* __restrict__ u,
    float* __restrict__ v)
{
    __shared__ float W1s[128 * 64];   // 32KB
    __shared__ float xs[32 * 64];     // 8KB

    const int t  = threadIdx.x;
    const int n0 = blockIdx.x * 32;

    #pragma unroll
    for (int r = 0; r < 32; r++) W1s[r * 256 + t] = W1[r * 256 + t];

    #pragma unroll
    for (int r = 0; r < 8; r++) {
        int idx  = r * 256 + t;
        int nn   = idx >> 6;
        int f    = idx & 63;
        int node = n0 + nn;
        xs[idx] = (node < NN) ? x[node * F + f] : 0.f;
    }
    __syncthreads();

    const int jc = (t & 31) * 2;   // column pair
    const int ng = t >> 5;         // node group 0..7

    float a0[4], a1[4], c0[4], c1[4];
    #pragma unroll
    for (int s = 0; s < 4; s++) { a0[s] = a1[s] = c0[s] = c1[s] = 0.f; }

    #pragma unroll 8
    for (int k = 0; k < F; k++) {
        float2 wa = *(const float2*)&W1s[k * F + jc];
        float2 wb = *(const float2*)&W1s[(F + k) * F + jc];
        #pragma unroll
        for (int s = 0; s < 4; s++) {
            float xk = xs[(ng + 8 * s) * F + k];
            a0[s] = fmaf(xk, wa.x, a0[s]);
            a1[s] = fmaf(xk, wa.y, a1[s]);
            c0[s] = fmaf(xk, wb.x, c0[s]);
            c1[s] = fmaf(xk, wb.y, c1[s]);
        }
    }

    const float bb0 = b1g[jc], bb1 = b1g[jc + 1];
    #pragma unroll
    for (int s = 0; s < 4; s++) {
        int node = n0 + ng + 8 * s;
        if (node < NN) {
            u[node * F + jc]     = a0[s] - c0[s] + bb0;
            u[node * F + jc + 1] = a1[s] - c1[s] + bb1;
            v[node * F + jc]     = c0[s];
            v[node * F + jc + 1] = c1[s];
        }
    }
}

// ---------------------------------------------------------------------------
// Zero-fill
// ---------------------------------------------------------------------------
__global__ __launch_bounds__(256) void zero_kernel(float* __restrict__ p)
{
    p[blockIdx.x * 256 + threadIdx.x] = 0.f;
}

// ---------------------------------------------------------------------------
// Edge kernel: per edge  h1 = relu(u[dst] + v[src]);  h2 = h1@W2 + b2;
//              atomicMax(out[dst], max(h2, 0))   (uint-reinterpret, all >= 0)
// 128 edges/block, 256 threads: tile = 4 edges x 8 cols per thread,
// inner product in packed fma.rn.f32x2.
// NOTE: edge_index is int32 (JAX x64 disabled -> jnp.int64 silently int32).
// ---------------------------------------------------------------------------
__global__ __launch_bounds__(256) void edge_kernel(
    const int* __restrict__ ei,         // [2, NE] int32
    const float* __restrict__ u,
    const float* __restrict__ v,
    const float* __restrict__ W2,       // [64,64]
    const float* __restrict__ b2g,      // [64]
    float* __restrict__ out)
{
    extern __shared__ float smem[];
    float* h1s = smem;                       // TE*PAD
    float* W2s = smem + TE * PAD;            // 64*64 (16B-aligned offset)
    float* b2s = W2s + 64 * 64;              // 64
    int*   si  = (int*)(b2s + 64);           // TE
    int*   di  = si + TE;                    // TE

    const int t  = threadIdx.x;
    const int e0 = blockIdx.x * TE;

    #pragma unroll
    for (int r = 0; r < 16; r++) W2s[r * 256 + t] = W2[r * 256 + t];
    if (t < 64) b2s[t] = b2g[t];
    if (t < TE)            si[t]      = ei[e0 + t];
    else if (t < 2 * TE)   di[t - TE] = ei[NE + e0 + (t - TE)];
    __syncthreads();

    // phase 1: h1 = relu(u[dst] + v[src]) -> smem
    #pragma unroll 4
    for (int r = 0; r < 32; r++) {
        int idx = r * 256 + t;
        int e   = idx >> 6;
        int f   = idx & 63;
        float val = u[di[e] * F + f] + v[si[e] * F + f];
        h1s[e * PAD + f] = fmaxf(val, 0.f);
    }
    __syncthreads();

    // phase 2: [128,64] x [64,64] GEMM, f32x2 packed
    const int tx = t & 7;    // col group: cols tx*8 .. tx*8+7
    const int ty = t >> 3;   // edge group: edges ty*4 .. ty*4+3

    unsigned long long acc[4][4];
    const unsigned long long* b2p = (const unsigned long long*)b2s;
    #pragma unroll
    for (int i = 0; i < 4; i++)
        #pragma unroll
        for (int p = 0; p < 4; p++)
            acc[i][p] = b2p[tx * 4 + p];

    #pragma unroll 4
    for (int k = 0; k < F; k++) {
        ulonglong2 wA = *(const ulonglong2*)&W2s[k * F + tx * 8];
        ulonglong2 wB = *(const ulonglong2*)&W2s[k * F + tx * 8 + 4];
        unsigned long long w[4] = {wA.x, wA.y, wB.x, wB.y};
        #pragma unroll
        for (int i = 0; i < 4; i++) {
            float h = h1s[(ty * 4 + i) * PAD + k];
            unsigned long long hh;
            unsigned hb = __float_as_uint(h);
            asm("mov.b64 %0, {%1, %1};" : "=l"(hh) : "r"(hb));
            #pragma unroll
            for (int p = 0; p < 4; p++)
                asm("fma.rn.f32x2 %0, %1, %2, %0;" : "+l"(acc[i][p]) : "l"(hh), "l"(w[p]));
        }
    }

    // epilogue: clamp at 0, atomicMax into out[dst]
    #pragma unroll
    for (int i = 0; i < 4; i++) {
        int e = ty * 4 + i;
        unsigned* dest = (unsigned*)(out + di[e] * F + tx * 8);
        #pragma unroll
        for (int p = 0; p < 4; p++) {
            unsigned lo = (unsigned)(acc[i][p] & 0xffffffffull);
            unsigned hi = (unsigned)(acc[i][p] >> 32);
            float flo = fmaxf(__uint_as_float(lo), 0.f);
            float fhi = fmaxf(__uint_as_float(hi), 0.f);
            atomicMax(dest + 2 * p,     __float_as_uint(flo));
            atomicMax(dest + 2 * p + 1, __float_as_uint(fhi));
        }
    }
}

// ---------------------------------------------------------------------------
// launch
// ---------------------------------------------------------------------------
extern "C" void kernel_launch(void* const* d_in, const int* in_sizes, int n_in,
                              void* d_out, int out_size)
{
    const float* x   = (const float*)d_in[0];
    const int*   ei  = (const int*)d_in[1];
    const float* W1  = (const float*)d_in[2];
    const float* b1  = (const float*)d_in[3];
    const float* W2  = (const float*)d_in[4];
    const float* b2  = (const float*)d_in[5];
    float* out = (float*)d_out;

    float *u, *v, *x1, *x2;
    cudaGetSymbolAddress((void**)&u,  g_u);
    cudaGetSymbolAddress((void**)&v,  g_v);
    cudaGetSymbolAddress((void**)&x1, g_x1);
    cudaGetSymbolAddress((void**)&x2, g_x2);

    const int smem_bytes = TE * PAD * 4 + 64 * 64 * 4 + 64 * 4 + 2 * TE * 4;
    cudaFuncSetAttribute(edge_kernel, cudaFuncAttributeMaxDynamicSharedMemorySize,
                         smem_bytes);

    const int node_blocks = (NN + 31) / 32;       // 1563
    const int zero_blocks = (NN * F) / 256;       // 12500
    const int edge_blocks = NE / TE;              // 6250

    const float* cur = x;
    float* bufs[NLAYERS] = {x1, x2, out};

    for (int l = 0; l < NLAYERS; l++) {
        float* y = bufs[l];
        node_kernel<<<node_blocks, 256>>>(cur, W1 + l * 128 * 64, b1 + l * 64, u, v);
        zero_kernel<<<zero_blocks, 256>>>(y);
        edge_kernel<<<edge_blocks, 256, smem_bytes>>>(ei, u, v,
                                                      W2 + l * 64 * 64, b2 + l * 64, y);
        cur = y;
    }
}

// round 3
// speedup vs baseline: 1.5837x; 1.5837x over previous
#include <cuda_runtime.h>

#define NN 50000
#define NE 800000
#define F  64
#define NLAYERS 3

#define TE  128         // edges per block in edge kernel
#define PAD 68          // h1 smem row pad (floats; 272B row stride, 16B aligned)

// ---------------- scratch (device globals; no allocation allowed) ----------
__device__ float g_u [NN * F];
__device__ float g_v [NN * F];
__device__ float g_x1[NN * F];
__device__ float g_x2[NN * F];
__device__ int   g_cnt [NN];      // degree histogram
__device__ int   g_part[NN];      // per-chunk exclusive scan
__device__ int   g_run [NN];      // running offsets for scatter
__device__ int   g_bsum[256];     // per-chunk totals
__device__ int   g_ssrc[NE];      // dst-sorted src
__device__ int   g_sdst[NE];      // dst-sorted dst

// ===========================================================================
// Prep: counting sort of edges by dst (once per launch, amortized 3 layers)
// ===========================================================================
__global__ __launch_bounds__(256) void zero_int_kernel(int* __restrict__ p)
{
    int i = blockIdx.x * 256 + threadIdx.x;
    if (i < NN) p[i] = 0;
}

__global__ __launch_bounds__(256) void hist_kernel(const int* __restrict__ ei,
                                                   int* __restrict__ cnt)
{
    int e = blockIdx.x * 256 + threadIdx.x;   // NE = 3125*256 exact
    atomicAdd(&cnt[ei[NE + e]], 1);
}

// block-wide exclusive scan of 256 ints; writes excl results + block total
__device__ __forceinline__ int block_scan_excl(int v, int t, int* wsum)
{
    int lane = t & 31, w = t >> 5;
    int s = v;
    #pragma unroll
    for (int d = 1; d < 32; d <<= 1) {
        int n = __shfl_up_sync(0xffffffffu, s, d);
        if (lane >= d) s += n;
    }
    if (lane == 31) wsum[w] = s;
    __syncthreads();
    if (w == 0) {
        int ws = (lane < 8) ? wsum[lane] : 0;
        #pragma unroll
        for (int d = 1; d < 8; d <<= 1) {
            int n = __shfl_up_sync(0xffffffffu, ws, d);
            if (lane >= d) ws += n;
        }
        if (lane < 8) wsum[lane] = ws;   // inclusive warp sums
    }
    __syncthreads();
    int base = (w > 0) ? wsum[w - 1] : 0;
    return s - v + base;                  // exclusive
}

__global__ __launch_bounds__(256) void scan1_kernel(const int* __restrict__ cnt,
                                                    int* __restrict__ part,
                                                    int* __restrict__ bsum)
{
    __shared__ int wsum[8];
    int t = threadIdx.x;
    int i = blockIdx.x * 256 + t;
    int v = (i < NN) ? cnt[i] : 0;
    int ex = block_scan_excl(v, t, wsum);
    if (i < NN) part[i] = ex;
    if (t == 255) bsum[blockIdx.x] = ex + v;   // block total
}

__global__ __launch_bounds__(256) void scan2_kernel(int* __restrict__ bsum, int n)
{
    __shared__ int wsum[8];
    int t = threadIdx.x;
    int v = (t < n) ? bsum[t] : 0;
    int ex = block_scan_excl(v, t, wsum);
    if (t < n) bsum[t] = ex;
}

__global__ __launch_bounds__(256) void scan3_kernel(const int* __restrict__ part,
                                                    const int* __restrict__ bsum,
                                                    int* __restrict__ run)
{
    int i = blockIdx.x * 256 + threadIdx.x;
    if (i < NN) run[i] = part[i] + bsum[blockIdx.x];
}

__global__ __launch_bounds__(256) void scatter_kernel(const int* __restrict__ ei,
                                                      int* __restrict__ run,
                                                      int* __restrict__ ssrc,
                                                      int* __restrict__ sdst)
{
    int e = blockIdx.x * 256 + threadIdx.x;
    int s = ei[e];
    int d = ei[NE + e];
    int pos = atomicAdd(&run[d], 1);
    ssrc[pos] = s;
    sdst[pos] = d;
}

// ===========================================================================
// Node kernel: u = x@(W1a - W1b) + b1 ;  v = x@W1b  (packed f32x2)
// Also zero-fills 2048 floats of this layer's output buffer y.
// ===========================================================================
__global__ __launch_bounds__(256) void node_kernel(
    const float* __restrict__ x,
    const float* __restrict__ W1,   // [128,64] row-major
    const float* __restrict__ b1g,  // [64]
    float* __restrict__ u,
    float* __restrict__ v,
    float* __restrict__ y)          // output buffer to zero
{
    __shared__ float W1s[128 * 64];   // 32KB
    __shared__ float xs[32 * 64];     // 8KB

    const int t  = threadIdx.x;
    const int n0 = blockIdx.x * 32;

    // zero-fill slice of y (NN*F divisible by 8; base<NN*F => base+8<=NN*F)
    {
        int base = blockIdx.x * 2048 + t * 8;
        if (base < NN * F) {
            float4 z = make_float4(0.f, 0.f, 0.f, 0.f);
            *(float4*)(y + base)     = z;
            *(float4*)(y + base + 4) = z;
        }
    }

    #pragma unroll
    for (int r = 0; r < 32; r++) W1s[r * 256 + t] = W1[r * 256 + t];

    #pragma unroll
    for (int r = 0; r < 8; r++) {
        int idx  = r * 256 + t;
        int nn   = idx >> 6;
        int f    = idx & 63;
        int node = n0 + nn;
        xs[idx] = (node < NN) ? x[node * F + f] : 0.f;
    }
    __syncthreads();

    const int jc = (t & 31) * 2;   // column pair
    const int ng = t >> 5;         // node group 0..7

    unsigned long long accA[4], accC[4];
    #pragma unroll
    for (int s = 0; s < 4; s++) { accA[s] = 0ull; accC[s] = 0ull; }

    #pragma unroll 8
    for (int k = 0; k < F; k++) {
        unsigned long long wa = *(const unsigned long long*)&W1s[k * F + jc];
        unsigned long long wb = *(const unsigned long long*)&W1s[(F + k) * F + jc];
        #pragma unroll
        for (int s = 0; s < 4; s++) {
            float xk = xs[(ng + 8 * s) * F + k];
            unsigned long long hh;
            unsigned hb = __float_as_uint(xk);
            asm("mov.b64 %0, {%1, %1};" : "=l"(hh) : "r"(hb));
            asm("fma.rn.f32x2 %0, %1, %2, %0;" : "+l"(accA[s]) : "l"(hh), "l"(wa));
            asm("fma.rn.f32x2 %0, %1, %2, %0;" : "+l"(accC[s]) : "l"(hh), "l"(wb));
        }
    }

    const float bb0 = b1g[jc], bb1 = b1g[jc + 1];
    #pragma unroll
    for (int s = 0; s < 4; s++) {
        int node = n0 + ng + 8 * s;
        if (node < NN) {
            unsigned a0u, a1u, c0u, c1u;
            asm("mov.b64 {%0, %1}, %2;" : "=r"(a0u), "=r"(a1u) : "l"(accA[s]));
            asm("mov.b64 {%0, %1}, %2;" : "=r"(c0u), "=r"(c1u) : "l"(accC[s]));
            float a0 = __uint_as_float(a0u), a1 = __uint_as_float(a1u);
            float c0 = __uint_as_float(c0u), c1 = __uint_as_float(c1u);
            u[node * F + jc]     = a0 - c0 + bb0;
            u[node * F + jc + 1] = a1 - c1 + bb1;
            v[node * F + jc]     = c0;
            v[node * F + jc + 1] = c1;
        }
    }
}

// ===========================================================================
// Edge kernel (dst-sorted edges):
//   h1 = relu(u[dst] + v[src]); h2 = h1@W2 + b2;
//   segmented max over dst within block, one atomicMax per (segment, col).
// ===========================================================================
__global__ __launch_bounds__(256) void edge_kernel(
    const int* __restrict__ ssrc,
    const int* __restrict__ sdst,
    const float* __restrict__ u,
    const float* __restrict__ v,
    const float* __restrict__ W2,       // [64,64]
    const float* __restrict__ b2g,      // [64]
    float* __restrict__ out)
{
    extern __shared__ float smem[];
    float* h1s = smem;                       // TE*PAD
    float* W2s = smem + TE * PAD;            // 64*64
    float* b2s = W2s + 64 * 64;              // 64
    int*   si  = (int*)(b2s + 64);           // TE
    int*   di  = si + TE;                    // TE

    const int t  = threadIdx.x;
    const int e0 = blockIdx.x * TE;

    #pragma unroll
    for (int r = 0; r < 16; r++) W2s[r * 256 + t] = W2[r * 256 + t];
    if (t < 64) b2s[t] = b2g[t];
    if (t < TE)            si[t]      = ssrc[e0 + t];
    else if (t < 2 * TE)   di[t - TE] = sdst[e0 + t - TE];
    __syncthreads();

    // phase 1: h1 = relu(u[dst] + v[src]) -> smem (float4 gathers)
    #pragma unroll 4
    for (int r = 0; r < 8; r++) {
        int idx = r * 256 + t;        // over 2048 float4 slots
        int e   = idx >> 4;           // edge
        int q   = idx & 15;           // float4 within row
        float4 uq = *(const float4*)(u + (size_t)di[e] * F + q * 4);
        float4 vq = *(const float4*)(v + (size_t)si[e] * F + q * 4);
        float4 h;
        h.x = fmaxf(uq.x + vq.x, 0.f);
        h.y = fmaxf(uq.y + vq.y, 0.f);
        h.z = fmaxf(uq.z + vq.z, 0.f);
        h.w = fmaxf(uq.w + vq.w, 0.f);
        *(float4*)&h1s[e * PAD + q * 4] = h;
    }
    __syncthreads();

    // phase 2: [128,64] x [64,64] GEMM, packed f32x2
    const int tx = t & 7;    // col group: cols tx*8 .. tx*8+7
    const int ty = t >> 3;   // edge group: edges ty*4 .. ty*4+3

    unsigned long long acc[4][4];
    const unsigned long long* b2p = (const unsigned long long*)b2s;
    #pragma unroll
    for (int i = 0; i < 4; i++)
        #pragma unroll
        for (int p = 0; p < 4; p++)
            acc[i][p] = b2p[tx * 4 + p];

    #pragma unroll 4
    for (int k = 0; k < F; k++) {
        ulonglong2 wA = *(const ulonglong2*)&W2s[k * F + tx * 8];
        ulonglong2 wB = *(const ulonglong2*)&W2s[k * F + tx * 8 + 4];
        unsigned long long w[4] = {wA.x, wA.y, wB.x, wB.y};
        #pragma unroll
        for (int i = 0; i < 4; i++) {
            float h = h1s[(ty * 4 + i) * PAD + k];
            unsigned long long hh;
            unsigned hb = __float_as_uint(h);
            asm("mov.b64 %0, {%1, %1};" : "=l"(hh) : "r"(hb));
            #pragma unroll
            for (int p = 0; p < 4; p++)
                asm("fma.rn.f32x2 %0, %1, %2, %0;" : "+l"(acc[i][p]) : "l"(hh), "l"(w[p]));
        }
    }

    // write raw h2 back into h1s (reuse), then segmented max per dst
    __syncthreads();
    #pragma unroll
    for (int i = 0; i < 4; i++)
        #pragma unroll
        for (int p = 0; p < 4; p++)
            *(unsigned long long*)&h1s[(ty * 4 + i) * PAD + tx * 8 + p * 2] = acc[i][p];
    __syncthreads();

    // reduction: thread handles col c over rows [g*32, g*32+32)
    {
        const int c  = t & 63;
        const int g  = t >> 6;
        const int r0 = g * 32;
        int   cur = di[r0];
        float m   = h1s[r0 * PAD + c];
        #pragma unroll 1
        for (int r = r0 + 1; r < r0 + 32; r++) {
            int   d2  = di[r];
            float val = h1s[r * PAD + c];
            if (d2 != cur) {
                atomicMax((unsigned*)out + (size_t)cur * F + c,
                          __float_as_uint(fmaxf(m, 0.f)));
                cur = d2;
                m   = val;
            } else {
                m = fmaxf(m, val);
            }
        }
        atomicMax((unsigned*)out + (size_t)cur * F + c,
                  __float_as_uint(fmaxf(m, 0.f)));
    }
}

// ===========================================================================
// launch
// ===========================================================================
extern "C" void kernel_launch(void* const* d_in, const int* in_sizes, int n_in,
                              void* d_out, int out_size)
{
    const float* x   = (const float*)d_in[0];
    const int*   ei  = (const int*)d_in[1];
    const float* W1  = (const float*)d_in[2];
    const float* b1  = (const float*)d_in[3];
    const float* W2  = (const float*)d_in[4];
    const float* b2  = (const float*)d_in[5];
    float* out = (float*)d_out;

    float *u, *v, *x1, *x2;
    int *cnt, *part, *run, *bsum, *ssrc, *sdst;
    cudaGetSymbolAddress((void**)&u,    g_u);
    cudaGetSymbolAddress((void**)&v,    g_v);
    cudaGetSymbolAddress((void**)&x1,   g_x1);
    cudaGetSymbolAddress((void**)&x2,   g_x2);
    cudaGetSymbolAddress((void**)&cnt,  g_cnt);
    cudaGetSymbolAddress((void**)&part, g_part);
    cudaGetSymbolAddress((void**)&run,  g_run);
    cudaGetSymbolAddress((void**)&bsum, g_bsum);
    cudaGetSymbolAddress((void**)&ssrc, g_ssrc);
    cudaGetSymbolAddress((void**)&sdst, g_sdst);

    const int smem_bytes = TE * PAD * 4 + 64 * 64 * 4 + 64 * 4 + 2 * TE * 4;
    cudaFuncSetAttribute(edge_kernel, cudaFuncAttributeMaxDynamicSharedMemorySize,
                         smem_bytes);

    const int nchunks     = (NN + 255) / 256;     // 196
    const int node_blocks = (NN + 31) / 32;       // 1563
    const int edge_blocks = NE / TE;              // 6250
    const int eth_blocks  = NE / 256;             // 3125

    // ---- prep: counting sort by dst (once) ----
    zero_int_kernel<<<nchunks, 256>>>(cnt);
    hist_kernel<<<eth_blocks, 256>>>(ei, cnt);
    scan1_kernel<<<nchunks, 256>>>(cnt, part, bsum);
    scan2_kernel<<<1, 256>>>(bsum, nchunks);
    scan3_kernel<<<nchunks, 256>>>(part, bsum, run);
    scatter_kernel<<<eth_blocks, 256>>>(ei, run, ssrc, sdst);

    // ---- layers ----
    const float* cur = x;
    float* bufs[NLAYERS] = {x1, x2, out};

    for (int l = 0; l < NLAYERS; l++) {
        float* y = bufs[l];
        node_kernel<<<node_blocks, 256>>>(cur, W1 + l * 128 * 64, b1 + l * 64,
                                          u, v, y);
        edge_kernel<<<edge_blocks, 256, smem_bytes>>>(ssrc, sdst, u, v,
                                                      W2 + l * 64 * 64,
                                                      b2 + l * 64, y);
        cur = y;
    }
}